// round 11
// baseline (speedup 1.0000x reference)
#include <cuda_runtime.h>
#include <cstdint>

#define N_NODES 50000
#define N_EDGES 800000
#define DIM     64
#define N_REL   16

// ---------------- scratch (device globals: allocation-free) ----------------
__device__ float g_proj[(size_t)N_REL * N_NODES * DIM];  // 204.8 MB
__device__ float g_denom[N_NODES];

// ---------------- helpers ----------------
__device__ __forceinline__ float fast_tanh(float x) {
    float xc = fminf(fmaxf(x, -15.f), 15.f);
    float t  = __expf(2.f * xc);
    return __fdividef(t - 1.f, t + 1.f);
}
__device__ __forceinline__ unsigned long long pack2(float x) {
    unsigned long long r;
    asm("mov.b64 %0, {%1, %1};" : "=l"(r) : "f"(x));
    return r;
}
__device__ __forceinline__ void ffma2(unsigned long long& d,
                                      unsigned long long a,
                                      unsigned long long b) {
    asm("fma.rn.f32x2 %0, %1, %2, %0;" : "+l"(d) : "l"(a), "l"(b));
}
__device__ __forceinline__ void unpack2(unsigned long long v, float& lo, float& hi) {
    asm("mov.b64 {%0, %1}, %2;" : "=f"(lo), "=f"(hi) : "l"(v));
}
__device__ __forceinline__ float leaky(float x) { return x >= 0.f ? x : 0.01f * x; }

// ---------------- launch #1: zero hnb accumulator + denom ----------------
__global__ void init_kernel(float* __restrict__ hnb) {
    int i = blockIdx.x * blockDim.x + threadIdx.x;
    if (i < N_NODES * DIM / 4) ((float4*)hnb)[i] = make_float4(0.f, 0.f, 0.f, 0.f);
    if (i < N_NODES) g_denom[i] = 0.f;
}

// ---------------- launches #2/#3: proj (EXACT R8 config — proven 10.7us/rel)
// 256 threads, tile = 192 nodes x 64 cols, 3 blocks/SM = 24 warps/SM.
// Thread (cg = tid&7, tr = tid>>3): nodes tr*6..tr*6+5,
// cols {2cg+16j, 2cg+16j+1 : j=0..3}, conflict-free W LDS.64.
#define PROJ_TN 192
__global__ void __launch_bounds__(256, 3) proj_kernel(const float* __restrict__ nfeat,
                                                      const float* __restrict__ relW,
                                                      int r_base) {
    __shared__ __align__(16) float Ws[64 * 64];          // 16 KB [d][col]
    __shared__ __align__(16) float Xs[64 * PROJ_TN];     // 48 KB transposed [d][node]

    const int r   = r_base + blockIdx.y;
    const int n0  = blockIdx.x * PROJ_TN;
    const int tid = threadIdx.x;

    {
        const float4* wsrc = (const float4*)(relW + (size_t)r * 4096);
        float4* wdst = (float4*)Ws;
        #pragma unroll
        for (int i = tid; i < 1024; i += 256) wdst[i] = wsrc[i];
    }
    if (tid < PROJ_TN) {
        int n = n0 + tid;
        if (n < N_NODES) {
            const float4* nr = (const float4*)(nfeat + (size_t)n * DIM);
            #pragma unroll
            for (int c4 = 0; c4 < 16; c4++) {
                float4 v = nr[c4];
                Xs[(c4 * 4 + 0) * PROJ_TN + tid] = v.x;
                Xs[(c4 * 4 + 1) * PROJ_TN + tid] = v.y;
                Xs[(c4 * 4 + 2) * PROJ_TN + tid] = v.z;
                Xs[(c4 * 4 + 3) * PROJ_TN + tid] = v.w;
            }
        } else {
            #pragma unroll
            for (int c = 0; c < 64; c++) Xs[c * PROJ_TN + tid] = 0.f;
        }
    }
    __syncthreads();

    const int cg = tid & 7;
    const int tr = tid >> 3;
    const float* wbase = Ws + cg * 2;      // + d*64 + 16*j
    const float* xbase = Xs + tr * 6;      // + d*PROJ_TN + m

    unsigned long long acc[6][4];
    #pragma unroll
    for (int m = 0; m < 6; m++)
        #pragma unroll
        for (int j = 0; j < 4; j++) acc[m][j] = 0ull;

    #pragma unroll 4
    for (int d = 0; d < 64; d++) {
        unsigned long long w2[4];
        #pragma unroll
        for (int j = 0; j < 4; j++)
            w2[j] = *(const unsigned long long*)(wbase + d * 64 + 16 * j);
        #pragma unroll
        for (int m = 0; m < 6; m++) {
            unsigned long long x2 = pack2(xbase[d * PROJ_TN + m]);
            #pragma unroll
            for (int j = 0; j < 4; j++) ffma2(acc[m][j], x2, w2[j]);
        }
    }

    #pragma unroll
    for (int m = 0; m < 6; m++) {
        int n = n0 + tr * 6 + m;
        if (n >= N_NODES) continue;
        float* orow = g_proj + ((size_t)r * N_NODES + n) * DIM + cg * 2;
        #pragma unroll
        for (int j = 0; j < 4; j++)
            *(unsigned long long*)(orow + 16 * j) = acc[m][j];
    }
}

// ---------------- launches #4/#5: att + aggregation, relation-half passes --
// Pass processes only edges with rlo <= etype < rhi: per-pass proj gather
// footprint = 102 MB < L2 (126 MB) -> re-touches of a proj row hit L2.
// 16 lanes per edge-pair (2 edges), predicated per edge.
__global__ void __launch_bounds__(256) att_fused_kernel(const float* __restrict__ efeat,
                                                        const float* __restrict__ nfeat,
                                                        const int* __restrict__ src,
                                                        const int* __restrict__ dst,
                                                        const int* __restrict__ etype,
                                                        float* __restrict__ hnb,
                                                        int rlo, int rhi) {
    int gt = blockIdx.x * blockDim.x + threadIdx.x;
    int p  = gt >> 4;                 // pair of edges
    int sl = threadIdx.x & 15;
    if (p >= N_EDGES / 2) return;     // N_EDGES even

    int2 r2 = ((const int2*)etype)[p];
    bool act0 = (r2.x >= rlo) && (r2.x < rhi);
    bool act1 = (r2.y >= rlo) && (r2.y < rhi);
    if (!act0 && !act1) return;

    int2 s2 = ((const int2*)src)[p];
    int2 d2 = ((const int2*)dst)[p];
    int e0 = 2 * p, e1 = 2 * p + 1;

    float4 tv0, hv0, ev0, tv1, hv1, ev1;
    if (act0) {
        tv0 = ((const float4*)(g_proj + ((size_t)r2.x * N_NODES + s2.x) * DIM))[sl];
        hv0 = ((const float4*)(g_proj + ((size_t)r2.x * N_NODES + d2.x) * DIM))[sl];
        ev0 = __ldcs(((const float4*)(efeat + (size_t)e0 * DIM)) + sl);
    }
    if (act1) {
        tv1 = ((const float4*)(g_proj + ((size_t)r2.y * N_NODES + s2.y) * DIM))[sl];
        hv1 = ((const float4*)(g_proj + ((size_t)r2.y * N_NODES + d2.y) * DIM))[sl];
        ev1 = __ldcs(((const float4*)(efeat + (size_t)e1 * DIM)) + sl);
    }

    float val0 = 0.f, val1 = 0.f;
    if (act0)
        val0 = tv0.x * fast_tanh(hv0.x + ev0.x)
             + tv0.y * fast_tanh(hv0.y + ev0.y)
             + tv0.z * fast_tanh(hv0.z + ev0.z)
             + tv0.w * fast_tanh(hv0.w + ev0.w);
    if (act1)
        val1 = tv1.x * fast_tanh(hv1.x + ev1.x)
             + tv1.y * fast_tanh(hv1.y + ev1.y)
             + tv1.z * fast_tanh(hv1.z + ev1.z)
             + tv1.w * fast_tanh(hv1.w + ev1.w);

    #pragma unroll
    for (int off = 8; off; off >>= 1) {
        val0 += __shfl_xor_sync(0xffffffffu, val0, off);
        val1 += __shfl_xor_sync(0xffffffffu, val1, off);
    }

    if (act0) {
        float ex0 = __expf(val0);
        if (sl == 0) atomicAdd(&g_denom[d2.x], ex0);
        float4 v0 = ((const float4*)(nfeat + (size_t)s2.x * DIM))[sl];
        atomicAdd(((float4*)(hnb + (size_t)d2.x * DIM)) + sl,
                  make_float4(ex0 * v0.x, ex0 * v0.y, ex0 * v0.z, ex0 * v0.w));
    }
    if (act1) {
        float ex1 = __expf(val1);
        if (sl == 0) atomicAdd(&g_denom[d2.y], ex1);
        float4 v1 = ((const float4*)(nfeat + (size_t)s2.y * DIM))[sl];
        atomicAdd(((float4*)(hnb + (size_t)d2.y * DIM)) + sl,
                  make_float4(ex1 * v1.x, ex1 * v1.y, ex1 * v1.z, ex1 * v1.w));
    }
}

// ---------------- launch #6: FUSED normalize + both bi-interaction GEMMs ---
__global__ void __launch_bounds__(128) epilogue_kernel(const float* __restrict__ nfeat,
                                                       float* __restrict__ hnb,
                                                       const float* __restrict__ W1,
                                                       const float* __restrict__ W2,
                                                       float* __restrict__ out) {
    __shared__ __align__(16) float W1s[64 * 64];   // 16 KB
    __shared__ __align__(16) float W2s[64 * 64];   // 16 KB
    __shared__ __align__(16) float S0[64 * 64];    // 16 KB transposed [d][node]
    __shared__ __align__(16) float S1[64 * 64];    // 16 KB

    const int n0  = blockIdx.x * 64;
    const int tid = threadIdx.x;

    {
        const float4* w1src = (const float4*)W1;
        const float4* w2src = (const float4*)W2;
        float4* w1dst = (float4*)W1s;
        float4* w2dst = (float4*)W2s;
        #pragma unroll
        for (int i = tid; i < 1024; i += 128) { w1dst[i] = w1src[i]; w2dst[i] = w2src[i]; }
    }
    {
        int nn = tid & 63;
        int n  = n0 + nn;
        if (n < N_NODES) {
            float den = g_denom[n];
            float inv = (den > 0.f) ? (1.f / den) : 0.f;
            const float4* a4 = (const float4*)(nfeat + (size_t)n * DIM);
            float4*       b4 = (float4*)(hnb + (size_t)n * DIM);
            for (int c4 = (tid >> 6); c4 < 16; c4 += 2) {
                float4 a = a4[c4];
                float4 b = b4[c4];
                b = make_float4(b.x * inv, b.y * inv, b.z * inv, b.w * inv);
                b4[c4] = b;                      // normalized hnb = output #1
                S0[(c4 * 4 + 0) * 64 + nn] = a.x + b.x;
                S0[(c4 * 4 + 1) * 64 + nn] = a.y + b.y;
                S0[(c4 * 4 + 2) * 64 + nn] = a.z + b.z;
                S0[(c4 * 4 + 3) * 64 + nn] = a.w + b.w;
                S1[(c4 * 4 + 0) * 64 + nn] = a.x * b.x;
                S1[(c4 * 4 + 1) * 64 + nn] = a.y * b.y;
                S1[(c4 * 4 + 2) * 64 + nn] = a.z * b.z;
                S1[(c4 * 4 + 3) * 64 + nn] = a.w * b.w;
            }
        } else {
            for (int c4 = (tid >> 6); c4 < 16; c4 += 2) {
                #pragma unroll
                for (int q = 0; q < 4; q++) {
                    S0[(c4 * 4 + q) * 64 + nn] = 0.f;
                    S1[(c4 * 4 + q) * 64 + nn] = 0.f;
                }
            }
        }
    }
    __syncthreads();

    const int cg = tid & 3;      // cols {2cg+8j}: conflict-free LDS.64
    const int tr = tid >> 2;
    const float* w1base = W1s + cg * 2;
    const float* w2base = W2s + cg * 2;

    unsigned long long acc1[2][8], acc2[2][8];
    #pragma unroll
    for (int m = 0; m < 2; m++)
        #pragma unroll
        for (int j = 0; j < 8; j++) { acc1[m][j] = 0ull; acc2[m][j] = 0ull; }

    #pragma unroll 4
    for (int d = 0; d < 64; d++) {
        unsigned long long w1v[8], w2v[8];
        #pragma unroll
        for (int j = 0; j < 8; j++) {
            w1v[j] = *(const unsigned long long*)(w1base + d * 64 + 8 * j);
            w2v[j] = *(const unsigned long long*)(w2base + d * 64 + 8 * j);
        }
        #pragma unroll
        for (int m = 0; m < 2; m++) {
            unsigned long long x0 = pack2(S0[d * 64 + tr * 2 + m]);
            unsigned long long x1 = pack2(S1[d * 64 + tr * 2 + m]);
            #pragma unroll
            for (int j = 0; j < 8; j++) {
                ffma2(acc1[m][j], x0, w1v[j]);
                ffma2(acc2[m][j], x1, w2v[j]);
            }
        }
    }

    #pragma unroll
    for (int m = 0; m < 2; m++) {
        int n = n0 + tr * 2 + m;
        if (n >= N_NODES) continue;
        float* orow = out + (size_t)n * DIM + cg * 2;
        #pragma unroll
        for (int j = 0; j < 8; j++) {
            float lo1, hi1, lo2, hi2;
            unpack2(acc1[m][j], lo1, hi1);
            unpack2(acc2[m][j], lo2, hi2);
            orow[8 * j]     = leaky(lo1) + leaky(lo2);
            orow[8 * j + 1] = leaky(hi1) + leaky(hi2);
        }
    }
}

// ---------------- launch ----------------
extern "C" void kernel_launch(void* const* d_in, const int* in_sizes, int n_in,
                              void* d_out, int out_size) {
    const float* nfeat = (const float*)d_in[0];
    const float* efeat = (const float*)d_in[1];
    const float* relW  = (const float*)d_in[2];
    const float* W1    = (const float*)d_in[3];
    const float* W2    = (const float*)d_in[4];
    const int*   src   = (const int*)d_in[5];
    const int*   dst   = (const int*)d_in[6];
    const int*   etype = (const int*)d_in[7];

    float* hnb  = (float*)d_out;
    float* out2 = (float*)d_out + (size_t)N_NODES * DIM;

    const int AB = (N_EDGES / 2 * 16 + 255) / 256;

    // #1
    init_kernel<<<(N_NODES * DIM / 4 + 255) / 256, 256>>>(hnb);
    // #2, #3  (R8-proven proj)
    dim3 g1((N_NODES + PROJ_TN - 1) / PROJ_TN, N_REL / 2);
    proj_kernel<<<g1, 256>>>(nfeat, relW, 0);
    proj_kernel<<<g1, 256>>>(nfeat, relW, 8);
    // #4, #5  <- ncu profiles #4 (att pass 0: relations 0..7)
    att_fused_kernel<<<AB, 256>>>(efeat, nfeat, src, dst, etype, hnb, 0, 8);
    att_fused_kernel<<<AB, 256>>>(efeat, nfeat, src, dst, etype, hnb, 8, 16);
    // #6
    epilogue_kernel<<<(N_NODES + 63) / 64, 128>>>(nfeat, hnb, W1, W2, out2);
}

// round 12
// speedup vs baseline: 1.3877x; 1.3877x over previous
#include <cuda_runtime.h>
#include <cstdint>

#define N_NODES 50000
#define N_EDGES 800000
#define DIM     64
#define N_REL   16

// ---------------- scratch (device globals: allocation-free) ----------------
__device__ float g_proj[(size_t)N_REL * N_NODES * DIM];  // 204.8 MB
__device__ float g_denom[N_NODES];

// ---------------- helpers ----------------
__device__ __forceinline__ float fast_tanh(float x) {
    float xc = fminf(fmaxf(x, -15.f), 15.f);
    float t  = __expf(2.f * xc);
    return __fdividef(t - 1.f, t + 1.f);
}
__device__ __forceinline__ unsigned long long pack2(float x) {
    unsigned long long r;
    asm("mov.b64 %0, {%1, %1};" : "=l"(r) : "f"(x));
    return r;
}
__device__ __forceinline__ void ffma2(unsigned long long& d,
                                      unsigned long long a,
                                      unsigned long long b) {
    asm("fma.rn.f32x2 %0, %1, %2, %0;" : "+l"(d) : "l"(a), "l"(b));
}
__device__ __forceinline__ void unpack2(unsigned long long v, float& lo, float& hi) {
    asm("mov.b64 {%0, %1}, %2;" : "=f"(lo), "=f"(hi) : "l"(v));
}
__device__ __forceinline__ float leaky(float x) { return x >= 0.f ? x : 0.01f * x; }

// ---------------- launch #1: zero hnb accumulator + denom ----------------
__global__ void init_kernel(float* __restrict__ hnb) {
    int i = blockIdx.x * blockDim.x + threadIdx.x;
    if (i < N_NODES * DIM / 4) ((float4*)hnb)[i] = make_float4(0.f, 0.f, 0.f, 0.f);
    if (i < N_NODES) g_denom[i] = 0.f;
}

// ---------------- launches #2/#3: proj (EXACT R8 config — proven) ----------
#define PROJ_TN 192
__global__ void __launch_bounds__(256, 3) proj_kernel(const float* __restrict__ nfeat,
                                                      const float* __restrict__ relW,
                                                      int r_base) {
    __shared__ __align__(16) float Ws[64 * 64];          // 16 KB [d][col]
    __shared__ __align__(16) float Xs[64 * PROJ_TN];     // 48 KB transposed [d][node]

    const int r   = r_base + blockIdx.y;
    const int n0  = blockIdx.x * PROJ_TN;
    const int tid = threadIdx.x;

    {
        const float4* wsrc = (const float4*)(relW + (size_t)r * 4096);
        float4* wdst = (float4*)Ws;
        #pragma unroll
        for (int i = tid; i < 1024; i += 256) wdst[i] = wsrc[i];
    }
    if (tid < PROJ_TN) {
        int n = n0 + tid;
        if (n < N_NODES) {
            const float4* nr = (const float4*)(nfeat + (size_t)n * DIM);
            #pragma unroll
            for (int c4 = 0; c4 < 16; c4++) {
                float4 v = nr[c4];
                Xs[(c4 * 4 + 0) * PROJ_TN + tid] = v.x;
                Xs[(c4 * 4 + 1) * PROJ_TN + tid] = v.y;
                Xs[(c4 * 4 + 2) * PROJ_TN + tid] = v.z;
                Xs[(c4 * 4 + 3) * PROJ_TN + tid] = v.w;
            }
        } else {
            #pragma unroll
            for (int c = 0; c < 64; c++) Xs[c * PROJ_TN + tid] = 0.f;
        }
    }
    __syncthreads();

    const int cg = tid & 7;
    const int tr = tid >> 3;
    const float* wbase = Ws + cg * 2;      // + d*64 + 16*j
    const float* xbase = Xs + tr * 6;      // + d*PROJ_TN + m

    unsigned long long acc[6][4];
    #pragma unroll
    for (int m = 0; m < 6; m++)
        #pragma unroll
        for (int j = 0; j < 4; j++) acc[m][j] = 0ull;

    #pragma unroll 4
    for (int d = 0; d < 64; d++) {
        unsigned long long w2[4];
        #pragma unroll
        for (int j = 0; j < 4; j++)
            w2[j] = *(const unsigned long long*)(wbase + d * 64 + 16 * j);
        #pragma unroll
        for (int m = 0; m < 6; m++) {
            unsigned long long x2 = pack2(xbase[d * PROJ_TN + m]);
            #pragma unroll
            for (int j = 0; j < 4; j++) ffma2(acc[m][j], x2, w2[j]);
        }
    }

    #pragma unroll
    for (int m = 0; m < 6; m++) {
        int n = n0 + tr * 6 + m;
        if (n >= N_NODES) continue;
        float* orow = g_proj + ((size_t)r * N_NODES + n) * DIM + cg * 2;
        #pragma unroll
        for (int j = 0; j < 4; j++)
            *(unsigned long long*)(orow + 16 * j) = acc[m][j];
    }
}

// ---------------- launch #4: att + aggregation (EXACT R9 config — proven) --
__global__ void __launch_bounds__(256) att_fused_kernel(const float* __restrict__ efeat,
                                                        const float* __restrict__ nfeat,
                                                        const int* __restrict__ src,
                                                        const int* __restrict__ dst,
                                                        const int* __restrict__ etype,
                                                        float* __restrict__ hnb) {
    int gt = blockIdx.x * blockDim.x + threadIdx.x;
    int p  = gt >> 4;                 // pair of edges
    int sl = threadIdx.x & 15;
    if (p >= N_EDGES / 2) return;     // N_EDGES even

    int2 s2 = ((const int2*)src)[p];
    int2 d2 = ((const int2*)dst)[p];
    int2 r2 = ((const int2*)etype)[p];
    int e0 = 2 * p, e1 = 2 * p + 1;

    const float4* t40 = (const float4*)(g_proj + ((size_t)r2.x * N_NODES + s2.x) * DIM);
    const float4* h40 = (const float4*)(g_proj + ((size_t)r2.x * N_NODES + d2.x) * DIM);
    const float4* t41 = (const float4*)(g_proj + ((size_t)r2.y * N_NODES + s2.y) * DIM);
    const float4* h41 = (const float4*)(g_proj + ((size_t)r2.y * N_NODES + d2.y) * DIM);

    float4 tv0 = t40[sl], hv0 = h40[sl];
    float4 tv1 = t41[sl], hv1 = h41[sl];
    float4 ev0 = __ldcs(((const float4*)(efeat + (size_t)e0 * DIM)) + sl);
    float4 ev1 = __ldcs(((const float4*)(efeat + (size_t)e1 * DIM)) + sl);

    float val0 = tv0.x * fast_tanh(hv0.x + ev0.x)
               + tv0.y * fast_tanh(hv0.y + ev0.y)
               + tv0.z * fast_tanh(hv0.z + ev0.z)
               + tv0.w * fast_tanh(hv0.w + ev0.w);
    float val1 = tv1.x * fast_tanh(hv1.x + ev1.x)
               + tv1.y * fast_tanh(hv1.y + ev1.y)
               + tv1.z * fast_tanh(hv1.z + ev1.z)
               + tv1.w * fast_tanh(hv1.w + ev1.w);

    #pragma unroll
    for (int off = 8; off; off >>= 1) {
        val0 += __shfl_xor_sync(0xffffffffu, val0, off);
        val1 += __shfl_xor_sync(0xffffffffu, val1, off);
    }

    float ex0 = __expf(val0);
    float ex1 = __expf(val1);

    if (sl == 0) {
        atomicAdd(&g_denom[d2.x], ex0);
        atomicAdd(&g_denom[d2.y], ex1);
    }
    {
        float4 v0 = ((const float4*)(nfeat + (size_t)s2.x * DIM))[sl];
        float4 v1 = ((const float4*)(nfeat + (size_t)s2.y * DIM))[sl];
        atomicAdd(((float4*)(hnb + (size_t)d2.x * DIM)) + sl,
                  make_float4(ex0 * v0.x, ex0 * v0.y, ex0 * v0.z, ex0 * v0.w));
        atomicAdd(((float4*)(hnb + (size_t)d2.y * DIM)) + sl,
                  make_float4(ex1 * v1.x, ex1 * v1.y, ex1 * v1.z, ex1 * v1.w));
    }
}

// ---------------- launch #5: epilogue v2 (normalize + both GEMMs) ----------
// 256 threads, 128-node tile, 2 blocks/SM (16 warps). Thread (cg=tid&7,
// tr=tid>>3): nodes tr*4..+3, col pairs {2cg+16j : j=0..3} per GEMM —
// conflict-free broadcast W LDS.64 (R8-proven pattern). Per-warp-d:
// 8 W-loads + 8 X-loads vs 32 FFMA2 -> balanced (was 36wf/16cyc).
#define EPI_TN 128
__global__ void __launch_bounds__(256, 2) epilogue_kernel(const float* __restrict__ nfeat,
                                                          float* __restrict__ hnb,
                                                          const float* __restrict__ W1,
                                                          const float* __restrict__ W2,
                                                          float* __restrict__ out) {
    __shared__ __align__(16) float W1s[64 * 64];     // 16 KB
    __shared__ __align__(16) float W2s[64 * 64];     // 16 KB
    __shared__ __align__(16) float S0[64 * EPI_TN];  // 32 KB transposed [d][node]
    __shared__ __align__(16) float S1[64 * EPI_TN];  // 32 KB

    const int n0  = blockIdx.x * EPI_TN;
    const int tid = threadIdx.x;

    {
        const float4* w1src = (const float4*)W1;
        const float4* w2src = (const float4*)W2;
        float4* w1dst = (float4*)W1s;
        float4* w2dst = (float4*)W2s;
        #pragma unroll
        for (int i = tid; i < 1024; i += 256) { w1dst[i] = w1src[i]; w2dst[i] = w2src[i]; }
    }
    {
        int nn   = tid & 127;
        int half = tid >> 7;           // c4 range [half*8, half*8+8)
        int n    = n0 + nn;
        if (n < N_NODES) {
            float den = g_denom[n];
            float inv = (den > 0.f) ? (1.f / den) : 0.f;
            const float4* a4 = (const float4*)(nfeat + (size_t)n * DIM);
            float4*       b4 = (float4*)(hnb + (size_t)n * DIM);
            #pragma unroll
            for (int c4 = half * 8; c4 < half * 8 + 8; c4++) {
                float4 a = a4[c4];
                float4 b = b4[c4];
                b = make_float4(b.x * inv, b.y * inv, b.z * inv, b.w * inv);
                b4[c4] = b;                      // normalized hnb = output #1
                S0[(c4 * 4 + 0) * EPI_TN + nn] = a.x + b.x;
                S0[(c4 * 4 + 1) * EPI_TN + nn] = a.y + b.y;
                S0[(c4 * 4 + 2) * EPI_TN + nn] = a.z + b.z;
                S0[(c4 * 4 + 3) * EPI_TN + nn] = a.w + b.w;
                S1[(c4 * 4 + 0) * EPI_TN + nn] = a.x * b.x;
                S1[(c4 * 4 + 1) * EPI_TN + nn] = a.y * b.y;
                S1[(c4 * 4 + 2) * EPI_TN + nn] = a.z * b.z;
                S1[(c4 * 4 + 3) * EPI_TN + nn] = a.w * b.w;
            }
        } else {
            #pragma unroll
            for (int c4 = half * 8; c4 < half * 8 + 8; c4++) {
                #pragma unroll
                for (int q = 0; q < 4; q++) {
                    S0[(c4 * 4 + q) * EPI_TN + nn] = 0.f;
                    S1[(c4 * 4 + q) * EPI_TN + nn] = 0.f;
                }
            }
        }
    }
    __syncthreads();

    const int cg = tid & 7;
    const int tr = tid >> 3;               // 0..31
    const float* w1base = W1s + cg * 2;    // + d*64 + 16*j
    const float* w2base = W2s + cg * 2;
    const float* xb0 = S0 + tr * 4;        // + d*EPI_TN + m
    const float* xb1 = S1 + tr * 4;

    unsigned long long acc1[4][4], acc2[4][4];
    #pragma unroll
    for (int m = 0; m < 4; m++)
        #pragma unroll
        for (int j = 0; j < 4; j++) { acc1[m][j] = 0ull; acc2[m][j] = 0ull; }

    #pragma unroll 4
    for (int d = 0; d < 64; d++) {
        unsigned long long w1v[4], w2v[4];
        #pragma unroll
        for (int j = 0; j < 4; j++) {
            w1v[j] = *(const unsigned long long*)(w1base + d * 64 + 16 * j);
            w2v[j] = *(const unsigned long long*)(w2base + d * 64 + 16 * j);
        }
        #pragma unroll
        for (int m = 0; m < 4; m++) {
            unsigned long long x0 = pack2(xb0[d * EPI_TN + m]);
            unsigned long long x1 = pack2(xb1[d * EPI_TN + m]);
            #pragma unroll
            for (int j = 0; j < 4; j++) {
                ffma2(acc1[m][j], x0, w1v[j]);
                ffma2(acc2[m][j], x1, w2v[j]);
            }
        }
    }

    #pragma unroll
    for (int m = 0; m < 4; m++) {
        int n = n0 + tr * 4 + m;
        if (n >= N_NODES) continue;
        float* orow = out + (size_t)n * DIM + cg * 2;
        #pragma unroll
        for (int j = 0; j < 4; j++) {
            float lo1, hi1, lo2, hi2;
            unpack2(acc1[m][j], lo1, hi1);
            unpack2(acc2[m][j], lo2, hi2);
            orow[16 * j]     = leaky(lo1) + leaky(lo2);
            orow[16 * j + 1] = leaky(hi1) + leaky(hi2);
        }
    }
}

// ---------------- launch ----------------
extern "C" void kernel_launch(void* const* d_in, const int* in_sizes, int n_in,
                              void* d_out, int out_size) {
    const float* nfeat = (const float*)d_in[0];
    const float* efeat = (const float*)d_in[1];
    const float* relW  = (const float*)d_in[2];
    const float* W1    = (const float*)d_in[3];
    const float* W2    = (const float*)d_in[4];
    const int*   src   = (const int*)d_in[5];
    const int*   dst   = (const int*)d_in[6];
    const int*   etype = (const int*)d_in[7];

    float* hnb  = (float*)d_out;
    float* out2 = (float*)d_out + (size_t)N_NODES * DIM;

    // #1
    init_kernel<<<(N_NODES * DIM / 4 + 255) / 256, 256>>>(hnb);
    // #2, #3  (R8-proven proj)
    dim3 g1((N_NODES + PROJ_TN - 1) / PROJ_TN, N_REL / 2);
    proj_kernel<<<g1, 256>>>(nfeat, relW, 0);
    proj_kernel<<<g1, 256>>>(nfeat, relW, 8);
    // #4  <- ncu profiles this launch (att, R9-proven)
    att_fused_kernel<<<(N_EDGES / 2 * 16 + 255) / 256, 256>>>(efeat, nfeat, src, dst, etype, hnb);
    // #5
    epilogue_kernel<<<(N_NODES + EPI_TN - 1) / EPI_TN, 256>>>(nfeat, hnb, W1, W2, out2);
}